// round 4
// baseline (speedup 1.0000x reference)
#include <cuda_runtime.h>
#include <mma.h>
#include <cstdint>

using namespace nvcuda;

// ----------------------------------------------------------------------------
// SparseLinear: y = x @ W + bias.  M=8192, N=4096, K=4096, fp32.
// Legacy-ISA path (compute_103 PTX — no tcgen05 available):
//   1) prep kernels round x and W to tf32 (rounded-nearest) into device scratch
//   2) tf32 wmma (mma.sync m16n16k8) GEMM, 128x128 CTA tile, BK=32,
//      double-buffered cp.async pipeline, bias fused in epilogue.
// ----------------------------------------------------------------------------

#define M_DIM 8192
#define N_DIM 4096
#define K_DIM 4096

#define BM 128
#define BN 128
#define BK 32
#define NIT (K_DIM / BK)      // 128 k-iterations

#define A_LD 40               // 32 + 8 pad (floats); 160B, 16B-multiple
#define B_LD 132              // 128 + 4 pad (floats); 528B, 16B-multiple

#define A_BUF_F (BM * A_LD)   // 5120 floats
#define B_BUF_F (BK * B_LD)   // 4224 floats
#define SMEM_FLOATS (2 * A_BUF_F + 2 * B_BUF_F)        // 18688
#define SMEM_BYTES  (SMEM_FLOATS * 4)                  // 74752

// tf32-rounded copies of the inputs (device scratch; no allocation at runtime)
__device__ float g_xr[(size_t)M_DIM * K_DIM];   // 128 MB
__device__ float g_wr[(size_t)K_DIM * N_DIM];   //  64 MB

// ------------------------------ helpers -------------------------------------
__device__ __forceinline__ void cp_async16(uint32_t smem_dst, const void* gsrc) {
    asm volatile("cp.async.cg.shared.global [%0], [%1], 16;\n"
                 :: "r"(smem_dst), "l"(gsrc));
}
__device__ __forceinline__ void cp_async_commit() {
    asm volatile("cp.async.commit_group;\n" ::: "memory");
}
__device__ __forceinline__ void cp_async_wait_all() {
    asm volatile("cp.async.wait_group 0;\n" ::: "memory");
}
__device__ __forceinline__ uint32_t smem_u32(const void* p) {
    return (uint32_t)__cvta_generic_to_shared(p);
}
__device__ __forceinline__ float tf32_round(float v) {
    float o;
    asm("cvt.rna.tf32.f32 %0, %1;" : "=f"(o) : "f"(v));
    return o;
}

// --------------------------- prep: round to tf32 ----------------------------
__global__ void __launch_bounds__(256) round_tf32_kernel(
    const float4* __restrict__ in, float4* __restrict__ out, int n4)
{
    int stride = gridDim.x * blockDim.x;
    for (int i = blockIdx.x * blockDim.x + threadIdx.x; i < n4; i += stride) {
        float4 v = in[i];
        v.x = tf32_round(v.x);
        v.y = tf32_round(v.y);
        v.z = tf32_round(v.z);
        v.w = tf32_round(v.w);
        out[i] = v;
    }
}

// -------------------------------- GEMM --------------------------------------
__global__ void __launch_bounds__(128, 2) gemm_tf32_kernel(
    const float* __restrict__ A,      // g_xr  [M, K]
    const float* __restrict__ B,      // g_wr  [K, N]
    const float* __restrict__ bias,
    float* __restrict__ out)
{
    extern __shared__ float sm[];
    float* As = sm;                    // 2 buffers of BM x A_LD
    float* Bs = sm + 2 * A_BUF_F;      // 2 buffers of BK x B_LD

    const int tid  = threadIdx.x;
    const int warp = tid >> 5;
    const int wm   = warp >> 1;        // 0..1  (64-row slab)
    const int wn   = warp & 1;         // 0..1  (64-col slab)

    const int n0 = blockIdx.x * BN;    // n-fast raster: W-tile reuse in L2
    const int m0 = blockIdx.y * BM;

    wmma::fragment<wmma::accumulator, 16, 16, 8, float> acc[4][4];
#pragma unroll
    for (int i = 0; i < 4; i++)
#pragma unroll
        for (int j = 0; j < 4; j++)
            wmma::fill_fragment(acc[i][j], 0.0f);

    // ---- software pipeline: prefetch tile `it` into buffer s ----
    auto prefetch = [&](int it, int s) {
        const int k0 = it * BK;
        // A tile: 128 rows x 128B  = 1024 x 16B chunks
#pragma unroll
        for (int r = 0; r < 8; r++) {
            int c   = tid + r * 128;
            int mm  = c >> 3;          // 0..127
            int seg = c & 7;           // 0..7
            const float* src = A + (size_t)(m0 + mm) * K_DIM + k0 + seg * 4;
            cp_async16(smem_u32(As + s * A_BUF_F + mm * A_LD + seg * 4), src);
        }
        // B tile: 32 rows x 512B = 1024 x 16B chunks
#pragma unroll
        for (int r = 0; r < 8; r++) {
            int c   = tid + r * 128;
            int kk  = c >> 5;          // 0..31
            int seg = c & 31;          // 0..31
            const float* src = B + (size_t)(k0 + kk) * N_DIM + n0 + seg * 4;
            cp_async16(smem_u32(Bs + s * B_BUF_F + kk * B_LD + seg * 4), src);
        }
        cp_async_commit();
    };

    prefetch(0, 0);

    for (int it = 0; it < NIT; it++) {
        const int s = it & 1;
        cp_async_wait_all();
        __syncthreads();
        if (it + 1 < NIT) prefetch(it + 1, s ^ 1);

        const float* as = As + s * A_BUF_F + wm * 64 * A_LD;
        const float* bs = Bs + s * B_BUF_F + wn * 64;

#pragma unroll
        for (int ks = 0; ks < 4; ks++) {           // 4 x k=8
            wmma::fragment<wmma::matrix_a, 16, 16, 8, wmma::precision::tf32,
                           wmma::row_major> af[4];
            wmma::fragment<wmma::matrix_b, 16, 16, 8, wmma::precision::tf32,
                           wmma::row_major> bf[4];
#pragma unroll
            for (int i = 0; i < 4; i++)
                wmma::load_matrix_sync(af[i], as + i * 16 * A_LD + ks * 8, A_LD);
#pragma unroll
            for (int j = 0; j < 4; j++)
                wmma::load_matrix_sync(bf[j], bs + ks * 8 * B_LD + j * 16, B_LD);
#pragma unroll
            for (int i = 0; i < 4; i++)
#pragma unroll
                for (int j = 0; j < 4; j++)
                    wmma::mma_sync(acc[i][j], af[i], bf[j], acc[i][j]);
        }
        __syncthreads();
    }

    // ---- epilogue: stage C in smem, add bias, vectorized global store ----
    float* C = sm;                     // reuse pipeline buffers (16896 < 18688)
#pragma unroll
    for (int i = 0; i < 4; i++)
#pragma unroll
        for (int j = 0; j < 4; j++)
            wmma::store_matrix_sync(
                C + (size_t)(wm * 64 + i * 16) * B_LD + wn * 64 + j * 16,
                acc[i][j], B_LD, wmma::mem_row_major);
    __syncthreads();

    const int m = tid;                 // one row per thread
    float* orow = out + (size_t)(m0 + m) * N_DIM + n0;
    const float* crow = C + (size_t)m * B_LD;
#pragma unroll
    for (int j = 0; j < BN; j += 4) {
        float4 c  = *reinterpret_cast<const float4*>(crow + j);
        float4 bv = *reinterpret_cast<const float4*>(bias + n0 + j);
        c.x += bv.x; c.y += bv.y; c.z += bv.z; c.w += bv.w;
        *reinterpret_cast<float4*>(orow + j) = c;
    }
}

// ------------------------------- host side ----------------------------------
extern "C" void kernel_launch(void* const* d_in, const int* in_sizes, int n_in,
                              void* d_out, int out_size) {
    const float* x    = (const float*)d_in[0];
    const float* W    = (const float*)d_in[1];
    const float* bias = (const float*)d_in[2];
    float* out = (float*)d_out;

    float* xr = nullptr;
    float* wr = nullptr;
    cudaGetSymbolAddress((void**)&xr, g_xr);
    cudaGetSymbolAddress((void**)&wr, g_wr);

    // 1) round inputs to tf32 (rounded-nearest) into scratch
    {
        int n4x = (M_DIM * K_DIM) / 4;
        int n4w = (K_DIM * N_DIM) / 4;
        round_tf32_kernel<<<2048, 256>>>((const float4*)x, (float4*)xr, n4x);
        round_tf32_kernel<<<2048, 256>>>((const float4*)W, (float4*)wr, n4w);
    }

    // 2) GEMM + fused bias
    static bool attr_set = false;
    if (!attr_set) {
        cudaFuncSetAttribute(gemm_tf32_kernel,
                             cudaFuncAttributeMaxDynamicSharedMemorySize,
                             SMEM_BYTES);
        attr_set = true;
    }
    dim3 grid(N_DIM / BN, M_DIM / BM);   // (32, 64), n-fast
    gemm_tf32_kernel<<<grid, 128, SMEM_BYTES>>>(xr, wr, bias, out);
}

// round 6
// speedup vs baseline: 1.4423x; 1.4423x over previous
#include <cuda_runtime.h>
#include <cstdint>

// ----------------------------------------------------------------------------
// SparseLinear: y = x @ W + bias.  M=8192, N=4096, K=4096, fp32.
// compute_103 base-ISA path (no tcgen05): hand-rolled mma.sync.m16n8k8.tf32
// with ldmatrix.x4.b16 fragment loads from XOR-swizzled smem, 4-stage cp.async
// pipeline, 128x256 CTA tile, fused bias epilogue.
// Prep: round x to tf32(RN); transpose+round W -> WT [N,K].
// ----------------------------------------------------------------------------

#define M_DIM 8192
#define N_DIM 4096
#define K_DIM 4096

#define BM 128
#define BN 256
#define BK 32
#define NIT (K_DIM / BK)              // 128
#define NSTAGES 4

#define A_STAGE_BYTES (BM * BK * 4)   // 16384
#define B_STAGE_BYTES (BN * BK * 4)   // 32768
#define STAGE_BYTES (A_STAGE_BYTES + B_STAGE_BYTES)   // 49152
#define SMEM_BYTES (NSTAGES * STAGE_BYTES)            // 196608

// device scratch: tf32-rounded x, and transposed+rounded W
__device__ float g_xr[(size_t)M_DIM * K_DIM];   // 128 MB
__device__ float g_wt[(size_t)N_DIM * K_DIM];   //  64 MB, WT[n][k]

// ------------------------------ helpers -------------------------------------
__device__ __forceinline__ void cp_async16(uint32_t smem_dst, const void* gsrc) {
    asm volatile("cp.async.cg.shared.global [%0], [%1], 16;\n"
                 :: "r"(smem_dst), "l"(gsrc));
}
__device__ __forceinline__ void cp_async_commit() {
    asm volatile("cp.async.commit_group;\n" ::: "memory");
}
template <int N>
__device__ __forceinline__ void cp_async_wait() {
    asm volatile("cp.async.wait_group %0;\n" :: "n"(N) : "memory");
}
__device__ __forceinline__ uint32_t smem_u32(const void* p) {
    return (uint32_t)__cvta_generic_to_shared(p);
}
__device__ __forceinline__ float tf32_round(float v) {
    float o;
    asm("cvt.rna.tf32.f32 %0, %1;" : "=f"(o) : "f"(v));
    return o;
}
__device__ __forceinline__ void ldsm_x4(uint32_t* r, uint32_t addr) {
    asm volatile("ldmatrix.sync.aligned.m8n8.x4.shared.b16 {%0,%1,%2,%3}, [%4];"
                 : "=r"(r[0]), "=r"(r[1]), "=r"(r[2]), "=r"(r[3]) : "r"(addr));
}
__device__ __forceinline__ void mma_tf32(float* d, const uint32_t* a,
                                         uint32_t b0, uint32_t b1) {
    asm volatile(
        "mma.sync.aligned.m16n8k8.row.col.f32.tf32.tf32.f32 "
        "{%0,%1,%2,%3}, {%4,%5,%6,%7}, {%8,%9}, {%0,%1,%2,%3};"
        : "+f"(d[0]), "+f"(d[1]), "+f"(d[2]), "+f"(d[3])
        : "r"(a[0]), "r"(a[1]), "r"(a[2]), "r"(a[3]), "r"(b0), "r"(b1));
}

// --------------------------- prep kernels -----------------------------------
__global__ void __launch_bounds__(256) round_tf32_kernel(
    const float4* __restrict__ in, float4* __restrict__ out, int n4)
{
    int stride = gridDim.x * blockDim.x;
    for (int i = blockIdx.x * blockDim.x + threadIdx.x; i < n4; i += stride) {
        float4 v = in[i];
        v.x = tf32_round(v.x);
        v.y = tf32_round(v.y);
        v.z = tf32_round(v.z);
        v.w = tf32_round(v.w);
        out[i] = v;
    }
}

// W [K,N] row-major -> WT [N,K] row-major, rounded to tf32
__global__ void __launch_bounds__(256) transpose_round_kernel(
    const float* __restrict__ W, float* __restrict__ WT)
{
    __shared__ float t[32][33];
    int bx = blockIdx.x;   // n tile
    int by = blockIdx.y;   // k tile
    int tx = threadIdx.x, ty = threadIdx.y;
    int n = bx * 32 + tx;
    int k = by * 32 + ty;
#pragma unroll
    for (int j = 0; j < 32; j += 8)
        t[ty + j][tx] = tf32_round(W[(size_t)(k + j) * N_DIM + n]);
    __syncthreads();
    int k2 = by * 32 + tx;
    int n2 = bx * 32 + ty;
#pragma unroll
    for (int j = 0; j < 32; j += 8)
        WT[(size_t)(n2 + j) * K_DIM + k2] = t[tx][ty + j];
}

// -------------------------------- GEMM --------------------------------------
__global__ void __launch_bounds__(256, 1) gemm_tf32_kernel(
    const float* __restrict__ A,      // g_xr [M,K]
    const float* __restrict__ B,      // g_wt [N,K]
    const float* __restrict__ bias,
    float* __restrict__ out)
{
    extern __shared__ char smem[];
    const uint32_t sbase = smem_u32(smem);

    const int tid  = threadIdx.x;
    const int warp = tid >> 5;
    const int lane = tid & 31;
    const int wm   = warp >> 2;       // 0..1 : 64-row slab
    const int wn   = warp & 3;        // 0..3 : 64-col slab

    const int n0 = blockIdx.x * BN;   // x fast -> n fast raster (L2 reuse)
    const int m0 = blockIdx.y * BM;

    // ---- per-thread ldmatrix geometry ----
    const int r7 = lane & 7;
    const int dA = lane >> 4;                 // A: chunk select (0/1)
    const int dB = (lane >> 3) & 1;           // B: chunk select (0/1)
    // A: 4 m16-tiles; lane -> row within tile
    uint32_t rowA[4];
#pragma unroll
    for (int i = 0; i < 4; i++)
        rowA[i] = (uint32_t)((wm * 64 + i * 16 + r7 + ((lane >> 3) & 1) * 8) * 128);
    // B: 4 ldsm.x4 each covering two n8-tiles (16 n-rows)
    uint32_t rowB[4];
#pragma unroll
    for (int j2 = 0; j2 < 4; j2++)
        rowB[j2] = (uint32_t)((wn * 64 + j2 * 16 + r7 + (lane >> 4) * 8) * 128);

    // ---- cp.async source pointers ----
    // A: thread t -> row t>>1, chunk base (t&1)*4, 4 chunks
    const int arow = tid >> 1;
    const int acb  = (tid & 1) * 4;
    const float* aptr = A + (size_t)(m0 + arow) * K_DIM + acb * 4;
    const uint32_t adst_row = sbase + (uint32_t)(arow * 128);
    // B: thread t -> n-row t, 8 chunks
    const float* bptr = B + (size_t)(n0 + tid) * K_DIM;
    const uint32_t bdst_row = sbase + A_STAGE_BYTES + (uint32_t)(tid * 128);

    auto prefetch = [&](int it, int s) {
        const uint32_t so = (uint32_t)(s * STAGE_BYTES);
        const float* ap = aptr + it * BK;
        const float* bp = bptr + it * BK;
#pragma unroll
        for (int c = 0; c < 4; c++) {
            int cc = acb + c;
            cp_async16(adst_row + so + (uint32_t)(((cc ^ (arow & 7)) * 16)),
                       ap + c * 4);
        }
#pragma unroll
        for (int c = 0; c < 8; c++) {
            cp_async16(bdst_row + so + (uint32_t)(((c ^ (tid & 7)) * 16)),
                       bp + c * 4);
        }
        cp_async_commit();
    };

    float acc[4][8][4];
#pragma unroll
    for (int i = 0; i < 4; i++)
#pragma unroll
        for (int j = 0; j < 8; j++)
#pragma unroll
            for (int q = 0; q < 4; q++)
                acc[i][j][q] = 0.0f;

    // ---- prologue: fill stages 0..2 ----
    prefetch(0, 0);
    prefetch(1, 1);
    prefetch(2, 2);

#pragma unroll 1
    for (int it = 0; it < NIT; it++) {
        const int s = it & (NSTAGES - 1);
        cp_async_wait<2>();
        __syncthreads();

        if (it + 3 < NIT) {
            prefetch(it + 3, (it + 3) & (NSTAGES - 1));
        } else {
            cp_async_commit();   // keep group accounting uniform
        }

        const uint32_t aoff = sbase + (uint32_t)(s * STAGE_BYTES);
        const uint32_t boff = aoff + A_STAGE_BYTES;

#pragma unroll
        for (int ks = 0; ks < 4; ks++) {
            const uint32_t oA = (uint32_t)((((ks << 1) | dA) ^ r7) << 4);
            const uint32_t oB = (uint32_t)((((ks << 1) | dB) ^ r7) << 4);
            uint32_t af[4][4];
#pragma unroll
            for (int i = 0; i < 4; i++)
                ldsm_x4(af[i], aoff + rowA[i] + oA);
            uint32_t bf[4][4];
#pragma unroll
            for (int j2 = 0; j2 < 4; j2++)
                ldsm_x4(bf[j2], boff + rowB[j2] + oB);
#pragma unroll
            for (int i = 0; i < 4; i++)
#pragma unroll
                for (int j = 0; j < 8; j++)
                    mma_tf32(acc[i][j], af[i],
                             bf[j >> 1][(j & 1) * 2],
                             bf[j >> 1][(j & 1) * 2 + 1]);
        }
    }

    // ---- epilogue: fused bias, direct STG.64 ----
    const int g   = lane >> 2;
    const int tig = lane & 3;
#pragma unroll
    for (int j = 0; j < 8; j++) {
        const int col = n0 + wn * 64 + j * 8 + tig * 2;
        const float2 bv = *reinterpret_cast<const float2*>(bias + col);
#pragma unroll
        for (int i = 0; i < 4; i++) {
            const int r0 = m0 + wm * 64 + i * 16 + g;
            float2 v0, v1;
            v0.x = acc[i][j][0] + bv.x;
            v0.y = acc[i][j][1] + bv.y;
            v1.x = acc[i][j][2] + bv.x;
            v1.y = acc[i][j][3] + bv.y;
            *reinterpret_cast<float2*>(out + (size_t)r0 * N_DIM + col) = v0;
            *reinterpret_cast<float2*>(out + (size_t)(r0 + 8) * N_DIM + col) = v1;
        }
    }
}

// ------------------------------- host side ----------------------------------
extern "C" void kernel_launch(void* const* d_in, const int* in_sizes, int n_in,
                              void* d_out, int out_size) {
    const float* x    = (const float*)d_in[0];
    const float* W    = (const float*)d_in[1];
    const float* bias = (const float*)d_in[2];
    float* out = (float*)d_out;

    float* xr = nullptr;
    float* wt = nullptr;
    cudaGetSymbolAddress((void**)&xr, g_xr);
    cudaGetSymbolAddress((void**)&wt, g_wt);

    // prep: round x; transpose+round W
    round_tf32_kernel<<<2048, 256>>>((const float4*)x, (float4*)xr,
                                     (M_DIM * K_DIM) / 4);
    transpose_round_kernel<<<dim3(N_DIM / 32, K_DIM / 32), dim3(32, 8)>>>(W, wt);

    cudaFuncSetAttribute(gemm_tf32_kernel,
                         cudaFuncAttributeMaxDynamicSharedMemorySize, SMEM_BYTES);
    dim3 grid(N_DIM / BN, M_DIM / BM);   // (16, 64), n-fast
    gemm_tf32_kernel<<<grid, 256, SMEM_BYTES>>>(xr, wt, bias, out);
}